// round 11
// baseline (speedup 1.0000x reference)
#include <cuda_runtime.h>
#include <cuda_fp16.h>
#include <cstdint>

// ---------------- problem constants ----------------
#define B_    8
#define K_    128
#define S_    256
#define NOUT  16384
#define M_    2048
#define BM    128
#define BN    128
#define BK    32
#define NTILES 2048
#define NST   6
#define STAGE_BYTES (BK * 256 * 2)            // A[32][256B] + B[32][256B] = 16KB
#define SM_TOTAL (NST * STAGE_BYTES)          // 96KB ring

// ---------------- scratch: fp16, same layout as sources ----------------
__device__ __align__(16) __half g_A[B_ * K_ * S_];   // [n][k][s]
__device__ __align__(16) __half g_B[K_ * NOUT];      // [k][j]

// ---------------- barrier state (self-restoring across replays) ----------------
__device__ unsigned g_bar_count = 0;
__device__ unsigned g_bar_phase = 0;

// ---------------- helpers ----------------
__device__ __forceinline__ uint32_t smem_u32(const void* p) {
    uint32_t a;
    asm("{ .reg .u64 t; cvta.to.shared.u64 t, %1; cvt.u32.u64 %0, t; }" : "=r"(a) : "l"(p));
    return a;
}
__device__ __forceinline__ void cp_async16(uint32_t saddr, const void* gaddr) {
    asm volatile("cp.async.cg.shared.global [%0], [%1], 16;" :: "r"(saddr), "l"(gaddr));
}
__device__ __forceinline__ void cp_commit() {
    asm volatile("cp.async.commit_group;" ::: "memory");
}
template <int N>
__device__ __forceinline__ void cp_wait() {
    asm volatile("cp.async.wait_group %0;" :: "n"(N) : "memory");
}
__device__ __forceinline__ void ldsm4t(uint32_t& r0, uint32_t& r1, uint32_t& r2, uint32_t& r3,
                                       uint32_t addr) {
    asm volatile("ldmatrix.sync.aligned.m8n8.x4.trans.shared.b16 {%0,%1,%2,%3}, [%4];"
                 : "=r"(r0), "=r"(r1), "=r"(r2), "=r"(r3) : "r"(addr));
}
__device__ __forceinline__ void mma16816(float* d, uint32_t a0, uint32_t a1, uint32_t a2,
                                         uint32_t a3, uint32_t b0, uint32_t b1) {
    asm volatile(
        "mma.sync.aligned.m16n8k16.row.col.f32.f16.f16.f32 "
        "{%0,%1,%2,%3}, {%4,%5,%6,%7}, {%8,%9}, {%0,%1,%2,%3};"
        : "+f"(d[0]), "+f"(d[1]), "+f"(d[2]), "+f"(d[3])
        : "r"(a0), "r"(a1), "r"(a2), "r"(a3), "r"(b0), "r"(b1));
}

#define TSWZ(k, c) ((c) ^ ((k) & 7))

// ---------------- fused persistent kernel ----------------
__global__ __launch_bounds__(256, 2)
void fused_kernel(const float* __restrict__ y, const float* __restrict__ W,
                  float* __restrict__ out) {
    extern __shared__ char smem[];
    const uint32_t sbase = smem_u32(smem);
    const int tid  = threadIdx.x;
    const int bid  = blockIdx.x;
    const int grid = gridDim.x;
    const int lane = tid & 31;
    const int w    = tid >> 5;
    const int wm   = w >> 2;
    const int wn   = w & 3;

    // ===== phase 1: streaming fp32 -> fp16 cast =====
    {
        const int nthr = grid << 8;
        for (int u = (bid << 8) + tid; u < 294912; u += nthr) {
            const float* s; __half* d;
            if (u < 262144) { s = W + (size_t)u * 8; d = g_B + (size_t)u * 8; }
            else { int v = u - 262144; s = y + (size_t)v * 8; d = g_A + (size_t)v * 8; }
            float4 v0 = ((const float4*)s)[0];
            float4 v1 = ((const float4*)s)[1];
            __half2 h0 = __floats2half2_rn(v0.x, v0.y);
            __half2 h1 = __floats2half2_rn(v0.z, v0.w);
            __half2 h2 = __floats2half2_rn(v1.x, v1.y);
            __half2 h3 = __floats2half2_rn(v1.z, v1.w);
            uint4 o;
            o.x = *(uint32_t*)&h0; o.y = *(uint32_t*)&h1;
            o.z = *(uint32_t*)&h2; o.w = *(uint32_t*)&h3;
            *(uint4*)d = o;
        }
    }

    // ===== phase 2: global barrier =====
    __syncthreads();
    if (tid == 0) {
        unsigned ph = *(volatile unsigned*)&g_bar_phase;
        __threadfence();
        unsigned t = atomicAdd(&g_bar_count, 1u);
        if (t == (unsigned)grid - 1u) {
            g_bar_count = 0;
            __threadfence();
            *(volatile unsigned*)&g_bar_phase = ph ^ 1u;
        } else {
            while (*(volatile unsigned*)&g_bar_phase == ph) __nanosleep(128);
        }
        __threadfence();
    }
    __syncthreads();

    // ===== precomputed per-thread constants =====
    // cp.async offsets: thread handles chunks (tid, tid+256) of 512, for A and B
    uint32_t sOff[2];        // swizzled smem offset within a stage
    uint32_t gOffA[2];       // element offset within A tile
    uint32_t gOffB[2];       // element offset within B tile
    #pragma unroll
    for (int it = 0; it < 2; ++it) {
        int ch = tid + it * 256;
        int k = ch >> 4, cc = ch & 15;
        sOff[it]  = (uint32_t)(k * 256 + (TSWZ(k, cc) << 4));
        gOffA[it] = (uint32_t)(k * S_ + cc * 8);
        gOffB[it] = (uint32_t)(k * NOUT + cc * 8);
    }
    // ldsm smem offsets (within stage): B (k16,ng) 4x, A (k16,mt) 8x
    uint32_t bOff[2][2], aOff[2][4];
    #pragma unroll
    for (int k16 = 0; k16 < 2; ++k16) {
        #pragma unroll
        for (int ng = 0; ng < 2; ++ng) {
            int kk = k16 * 16 + (lane & 7) + ((lane >> 3) & 1) * 8;
            int nn = wn * 32 + ng * 16 + ((lane >> 4) & 1) * 8;
            bOff[k16][ng] = (uint32_t)(BK * 256 + kk * 256 + (TSWZ(kk, nn >> 3) << 4));
        }
        #pragma unroll
        for (int mt = 0; mt < 4; ++mt) {
            int kk = k16 * 16 + (lane & 7) + ((lane >> 4) & 1) * 8;
            int mm = wm * 64 + mt * 16 + ((lane >> 3) & 1) * 8;
            aOff[k16][mt] = (uint32_t)(kk * 256 + (TSWZ(kk, mm >> 3) << 4));
        }
    }
    // epilogue constants: per nt, j-decomposition minus bx part
    uint32_t eOff[4];        // (p_local)*4096 + q*64 + r  for col within tile
    #pragma unroll
    for (int nt = 0; nt < 4; ++nt) {
        int col = wn * 32 + nt * 8 + ((lane & 3) << 1);
        eOff[nt] = (uint32_t)((col >> 4) * 4096 + (((col >> 2) & 3) << 6) + (col & 3));
    }
    const int sgb = wm * 64 + (lane >> 2);    // + mt*16 (+8) + mcol

    // ===== phase 3: persistent GEMM, 6-stage chunk ring =====
    const int ntiles = (NTILES - bid + grid - 1) / grid;
    const int C = ntiles * 4;

    float acc[4][4][4];
    #pragma unroll
    for (int i = 0; i < 4; ++i)
        #pragma unroll
        for (int j = 0; j < 4; ++j)
            #pragma unroll
            for (int k = 0; k < 4; ++k)
                acc[i][j][k] = 0.0f;

    auto issue = [&](int c) {
        int ti = bid + (c >> 2) * grid;
        int kb = c & 3;
        int by = ti >> 7, bx = ti & 127;
        const __half* gA = g_A + (by >> 1) * (K_ * S_) + (by & 1) * 128 + kb * (BK * S_);
        const __half* gB = g_B + bx * BN + kb * (BK * NOUT);
        const uint32_t st = sbase + (c % NST) * STAGE_BYTES;
        #pragma unroll
        for (int it = 0; it < 2; ++it) {
            cp_async16(st + sOff[it], gA + gOffA[it]);
            cp_async16(st + BK * 256 + sOff[it], gB + gOffB[it]);
        }
    };

    auto compute = [&](uint32_t st) {
        #pragma unroll
        for (int k16 = 0; k16 < 2; ++k16) {
            uint32_t br[4][2];
            #pragma unroll
            for (int ng = 0; ng < 2; ++ng) {
                uint32_t b0, b1, b2, b3;
                ldsm4t(b0, b1, b2, b3, st + bOff[k16][ng]);
                br[ng * 2][0] = b0;     br[ng * 2][1] = b1;
                br[ng * 2 + 1][0] = b2; br[ng * 2 + 1][1] = b3;
            }
            #pragma unroll
            for (int mt = 0; mt < 4; ++mt) {
                uint32_t a0, a1, a2, a3;
                ldsm4t(a0, a1, a2, a3, st + aOff[k16][mt]);
                #pragma unroll
                for (int nt = 0; nt < 4; ++nt)
                    mma16816(acc[mt][nt], a0, a1, a2, a3, br[nt][0], br[nt][1]);
            }
        }
    };

    auto epilogue = [&](int ti) {
        int by = ti >> 7, bx = ti & 127;
        int mcol = (by & 1) * 128;
        float* obase = out + (size_t)(by >> 1) * 4194304 + (uint32_t)bx * 32768u;
        #pragma unroll
        for (int mt = 0; mt < 4; ++mt) {
            int sg0 = mcol + sgb + mt * 16;
            uint32_t rowOff0 = (uint32_t)((sg0 >> 4) * 256 + (sg0 & 15) * 4);
            int sg1 = sg0 + 8;
            uint32_t rowOff1 = (uint32_t)((sg1 >> 4) * 256 + (sg1 & 15) * 4);
            #pragma unroll
            for (int nt = 0; nt < 4; ++nt) {
                *(float2*)(obase + eOff[nt] + rowOff0) =
                    make_float2(acc[mt][nt][0], acc[mt][nt][1]);
                *(float2*)(obase + eOff[nt] + rowOff1) =
                    make_float2(acc[mt][nt][2], acc[mt][nt][3]);
            }
        }
        #pragma unroll
        for (int i = 0; i < 4; ++i)
            #pragma unroll
            for (int jj = 0; jj < 4; ++jj)
                #pragma unroll
                for (int k = 0; k < 4; ++k)
                    acc[i][jj][k] = 0.0f;
    };

    // prologue: fill 5 of 6 ring stages
    #pragma unroll
    for (int c = 0; c < NST - 1; ++c) {
        if (c < C) issue(c);
        cp_commit();
    }

    // steady state: ONE barrier per chunk
    int stage = 0;
    for (int c = 0; c < C; ++c) {
        cp_wait<NST - 2>();
        __syncthreads();
        int cn = c + NST - 1;
        if (cn < C) issue(cn);          // writes stage (c-1)%NST: free since sync
        cp_commit();
        compute(sbase + stage * STAGE_BYTES);
        if ((c & 3) == 3) epilogue(bid + (c >> 2) * grid);
        if (++stage == NST) stage = 0;
    }
}

// ---------------- launch ----------------
extern "C" void kernel_launch(void* const* d_in, const int* in_sizes, int n_in,
                              void* d_out, int out_size) {
    const float* y = (const float*)d_in[0];   // [8][128][256]
    const float* W = (const float*)d_in[1];   // [128][16384]
    float* out = (float*)d_out;

    cudaFuncSetAttribute(fused_kernel,
                         cudaFuncAttributeMaxDynamicSharedMemorySize, SM_TOTAL);
    int nb = 0, sms = 0;
    cudaOccupancyMaxActiveBlocksPerMultiprocessor(&nb, fused_kernel, 256, SM_TOTAL);
    cudaDeviceGetAttribute(&sms, cudaDevAttrMultiProcessorCount, 0);
    int grid = nb * sms;
    if (grid > NTILES) grid = NTILES;
    if (grid < 1) grid = 1;

    fused_kernel<<<grid, 256, SM_TOTAL>>>(y, W, out);
}

// round 12
// speedup vs baseline: 1.0375x; 1.0375x over previous
#include <cuda_runtime.h>
#include <cuda_fp16.h>
#include <cstdint>

// ---------------- problem constants ----------------
#define B_    8
#define K_    128
#define S_    256
#define NOUT  16384
#define BM    128
#define BN    128
#define BK    64
#define NST   4
#define STAGE_BYTES (BK * 256)                // B chunk: 64 k-rows x 256B = 16KB
#define A_OFF (NST * STAGE_BYTES)             // A resident at 64KB
#define SM_TOTAL (A_OFF + 32768)              // 96KB

// ---------------- scratch: only W needs pre-cast ----------------
__device__ __align__(16) __half g_B[K_ * NOUT];      // [k][j]  4MB

__device__ unsigned g_bar_count = 0;
__device__ unsigned g_bar_phase = 0;

// ---------------- helpers ----------------
__device__ __forceinline__ uint32_t smem_u32(const void* p) {
    uint32_t a;
    asm("{ .reg .u64 t; cvta.to.shared.u64 t, %1; cvt.u32.u64 %0, t; }" : "=r"(a) : "l"(p));
    return a;
}
__device__ __forceinline__ void cp_async16(uint32_t saddr, const void* gaddr) {
    asm volatile("cp.async.cg.shared.global [%0], [%1], 16;" :: "r"(saddr), "l"(gaddr));
}
__device__ __forceinline__ void cp_commit() {
    asm volatile("cp.async.commit_group;" ::: "memory");
}
template <int N>
__device__ __forceinline__ void cp_wait() {
    asm volatile("cp.async.wait_group %0;" :: "n"(N) : "memory");
}
__device__ __forceinline__ void ldsm4t(uint32_t& r0, uint32_t& r1, uint32_t& r2, uint32_t& r3,
                                       uint32_t addr) {
    asm volatile("ldmatrix.sync.aligned.m8n8.x4.trans.shared.b16 {%0,%1,%2,%3}, [%4];"
                 : "=r"(r0), "=r"(r1), "=r"(r2), "=r"(r3) : "r"(addr));
}
__device__ __forceinline__ void mma16816(float* d, uint32_t a0, uint32_t a1, uint32_t a2,
                                         uint32_t a3, uint32_t b0, uint32_t b1) {
    asm volatile(
        "mma.sync.aligned.m16n8k16.row.col.f32.f16.f16.f32 "
        "{%0,%1,%2,%3}, {%4,%5,%6,%7}, {%8,%9}, {%0,%1,%2,%3};"
        : "+f"(d[0]), "+f"(d[1]), "+f"(d[2]), "+f"(d[3])
        : "r"(a0), "r"(a1), "r"(a2), "r"(a3), "r"(b0), "r"(b1));
}

#define TSWZ(k, c) ((c) ^ ((k) & 7))

// ---------------- fused persistent kernel ----------------
__global__ __launch_bounds__(256, 2)
void fused_kernel(const float* __restrict__ y, const float* __restrict__ W,
                  float* __restrict__ out) {
    extern __shared__ char smem[];
    const uint32_t sbase = smem_u32(smem);
    const int tid  = threadIdx.x;
    const int bid  = blockIdx.x;
    const int grid = gridDim.x;
    const int lane = tid & 31;
    const int w    = tid >> 5;
    const int wm   = w >> 2;
    const int wn   = w & 3;

    // row-affine work assignment
    const int row   = bid & 15;            // by: 0..15
    const int slot  = bid >> 4;
    const int slots = grid >> 4;
    const int nn    = row >> 1;            // batch
    const int mcol  = (row & 1) * 128;
    const int bx0   = (slot * 128) / slots;
    const int bx1   = ((slot + 1) * 128) / slots;

    // ===== issue A staging: y strip fp32 [128k][128m] -> smem[0..64KB) =====
    {
        const float* ya = y + (size_t)nn * 32768 + mcol;
        #pragma unroll
        for (int it = 0; it < 16; ++it) {
            int cid = tid + it * 256;             // 0..4095 16B chunks
            int k = cid >> 5, cc = cid & 31;
            cp_async16(sbase + k * 512 + ((cc ^ (k & 7)) << 4),
                       ya + (size_t)k * 256 + cc * 4);
        }
        cp_commit();
    }

    // ===== W cast: fp32 -> fp16 (grid-strided) =====
    {
        const int nthr = grid << 8;
        for (int u = (bid << 8) + tid; u < 262144; u += nthr) {
            float4 v0 = ((const float4*)(W + (size_t)u * 8))[0];
            float4 v1 = ((const float4*)(W + (size_t)u * 8))[1];
            __half2 h0 = __floats2half2_rn(v0.x, v0.y);
            __half2 h1 = __floats2half2_rn(v0.z, v0.w);
            __half2 h2 = __floats2half2_rn(v1.x, v1.y);
            __half2 h3 = __floats2half2_rn(v1.z, v1.w);
            uint4 o;
            o.x = *(uint32_t*)&h0; o.y = *(uint32_t*)&h1;
            o.z = *(uint32_t*)&h2; o.w = *(uint32_t*)&h3;
            *(uint4*)(g_B + (size_t)u * 8) = o;
        }
    }

    // ===== convert A strip to resident fp16 [128k][256B] at A_OFF =====
    cp_wait<0>();
    __syncthreads();
    {
        const int k = tid >> 1, half = tid & 1;
        const uint32_t rbase = sbase + k * 512;
        const uint32_t wbase = sbase + A_OFF + k * 256;
        #pragma unroll
        for (int j = 0; j < 8; ++j) {
            int c0 = half * 16 + 2 * j;
            float4 v0 = *(float4*)(smem + (rbase - sbase) + ((c0 ^ (k & 7)) << 4));
            float4 v1 = *(float4*)(smem + (rbase - sbase) + (((c0 + 1) ^ (k & 7)) << 4));
            __half2 h0 = __floats2half2_rn(v0.x, v0.y);
            __half2 h1 = __floats2half2_rn(v0.z, v0.w);
            __half2 h2 = __floats2half2_rn(v1.x, v1.y);
            __half2 h3 = __floats2half2_rn(v1.z, v1.w);
            uint4 o;
            o.x = *(uint32_t*)&h0; o.y = *(uint32_t*)&h1;
            o.z = *(uint32_t*)&h2; o.w = *(uint32_t*)&h3;
            *(uint4*)(smem + (wbase - sbase) + (TSWZ(k, half * 8 + j) << 4)) = o;
        }
    }
    __syncthreads();

    // ===== global barrier (W visibility) =====
    if (tid == 0) {
        unsigned ph = *(volatile unsigned*)&g_bar_phase;
        __threadfence();
        unsigned t = atomicAdd(&g_bar_count, 1u);
        if (t == (unsigned)grid - 1u) {
            g_bar_count = 0;
            __threadfence();
            *(volatile unsigned*)&g_bar_phase = ph ^ 1u;
        } else {
            while (*(volatile unsigned*)&g_bar_phase == ph) __nanosleep(128);
        }
        __threadfence();
    }
    __syncthreads();

    // ===== precomputed offsets =====
    uint32_t sOffB[4], gOffB[4];         // cp.async: 1024 chunks/stage, 4/thread
    #pragma unroll
    for (int it = 0; it < 4; ++it) {
        int cid = tid + it * 256;
        int k = cid >> 4, cc = cid & 15;
        sOffB[it] = (uint32_t)(k * 256 + (TSWZ(k, cc) << 4));
        gOffB[it] = (uint32_t)(k * NOUT + cc * 8);
    }
    uint32_t aOff0[4], bOff0[2];         // k16=0 bases; +k16*4096 folds to immediates
    {
        int kkA = (lane & 7) + ((lane >> 4) & 1) * 8;
        #pragma unroll
        for (int mt = 0; mt < 4; ++mt) {
            int mm = wm * 64 + mt * 16 + ((lane >> 3) & 1) * 8;
            aOff0[mt] = (uint32_t)(A_OFF + kkA * 256 + (TSWZ(kkA, mm >> 3) << 4));
        }
        int kkB = (lane & 7) + ((lane >> 3) & 1) * 8;
        #pragma unroll
        for (int ng = 0; ng < 2; ++ng) {
            int nnc = wn * 32 + ng * 16 + ((lane >> 4) & 1) * 8;
            bOff0[ng] = (uint32_t)(kkB * 256 + (TSWZ(kkB, nnc >> 3) << 4));
        }
    }
    uint32_t eOff[4];
    #pragma unroll
    for (int nt = 0; nt < 4; ++nt) {
        int col = wn * 32 + nt * 8 + ((lane & 3) << 1);
        eOff[nt] = (uint32_t)((col >> 4) * 4096 + (((col >> 2) & 3) << 6) + (col & 3));
    }
    const int sgb = mcol + wm * 64 + (lane >> 2);

    // ===== persistent GEMM: B-only 4-stage ring, BK=64 =====
    const int C = (bx1 - bx0) * 2;       // chunks (2 per tile)

    float acc[4][4][4];
    #pragma unroll
    for (int i = 0; i < 4; ++i)
        #pragma unroll
        for (int j = 0; j < 4; ++j)
            #pragma unroll
            for (int k = 0; k < 4; ++k)
                acc[i][j][k] = 0.0f;

    auto issue = [&](int c) {
        const __half* gB = g_B + (size_t)(bx0 + (c >> 1)) * BN + (c & 1) * (BK * NOUT);
        const uint32_t st = sbase + (c & (NST - 1)) * STAGE_BYTES;
        #pragma unroll
        for (int it = 0; it < 4; ++it)
            cp_async16(st + sOffB[it], gB + gOffB[it]);
    };

    auto compute = [&](uint32_t st, int kb) {
        const uint32_t aB = sbase + kb * 16384;
        #pragma unroll
        for (int k16 = 0; k16 < 4; ++k16) {
            uint32_t br[4][2];
            #pragma unroll
            for (int ng = 0; ng < 2; ++ng) {
                uint32_t b0, b1, b2, b3;
                ldsm4t(b0, b1, b2, b3, st + bOff0[ng] + k16 * 4096);
                br[ng * 2][0] = b0;     br[ng * 2][1] = b1;
                br[ng * 2 + 1][0] = b2; br[ng * 2 + 1][1] = b3;
            }
            #pragma unroll
            for (int mt = 0; mt < 4; ++mt) {
                uint32_t a0, a1, a2, a3;
                ldsm4t(a0, a1, a2, a3, aB + aOff0[mt] + k16 * 4096);
                #pragma unroll
                for (int nt = 0; nt < 4; ++nt)
                    mma16816(acc[mt][nt], a0, a1, a2, a3, br[nt][0], br[nt][1]);
            }
        }
    };

    auto epilogue = [&](int bx) {
        float* obase = out + (size_t)nn * 4194304 + (uint32_t)bx * 32768u;
        #pragma unroll
        for (int mt = 0; mt < 4; ++mt) {
            int sg0 = sgb + mt * 16;
            uint32_t r0 = (uint32_t)((sg0 >> 4) * 256 + (sg0 & 15) * 4);
            int sg1 = sg0 + 8;
            uint32_t r1 = (uint32_t)((sg1 >> 4) * 256 + (sg1 & 15) * 4);
            #pragma unroll
            for (int nt = 0; nt < 4; ++nt) {
                *(float2*)(obase + eOff[nt] + r0) =
                    make_float2(acc[mt][nt][0], acc[mt][nt][1]);
                *(float2*)(obase + eOff[nt] + r1) =
                    make_float2(acc[mt][nt][2], acc[mt][nt][3]);
            }
        }
        #pragma unroll
        for (int i = 0; i < 4; ++i)
            #pragma unroll
            for (int jj = 0; jj < 4; ++jj)
                #pragma unroll
                for (int k = 0; k < 4; ++k)
                    acc[i][jj][k] = 0.0f;
    };

    // prologue: fill 3 of 4 ring stages
    #pragma unroll
    for (int c = 0; c < NST - 1; ++c) {
        if (c < C) issue(c);
        cp_commit();
    }

    // steady state: one barrier per 64-k chunk
    for (int c = 0; c < C; ++c) {
        cp_wait<NST - 2>();
        __syncthreads();
        int cn = c + NST - 1;
        if (cn < C) issue(cn);
        cp_commit();
        compute(sbase + (c & (NST - 1)) * STAGE_BYTES, c & 1);
        if (c & 1) epilogue(bx0 + (c >> 1));
    }
}

// ---------------- launch ----------------
extern "C" void kernel_launch(void* const* d_in, const int* in_sizes, int n_in,
                              void* d_out, int out_size) {
    const float* y = (const float*)d_in[0];   // [8][128][256]
    const float* W = (const float*)d_in[1];   // [128][16384]
    float* out = (float*)d_out;

    cudaFuncSetAttribute(fused_kernel,
                         cudaFuncAttributeMaxDynamicSharedMemorySize, SM_TOTAL);
    int nb = 0, sms = 0;
    cudaOccupancyMaxActiveBlocksPerMultiprocessor(&nb, fused_kernel, 256, SM_TOTAL);
    cudaDeviceGetAttribute(&sms, cudaDevAttrMultiProcessorCount, 0);
    int grid = (nb * sms) & ~15;     // multiple of 16 rows
    if (grid < 16) grid = 16;
    if (grid > 2048) grid = 2048;

    fused_kernel<<<grid, 256, SM_TOTAL>>>(y, W, out);
}